// round 1
// baseline (speedup 1.0000x reference)
#include <cuda_runtime.h>
#include <math.h>

#define D   128
#define D4  512
#define MAXN 100000

// ---------------- scratch (no allocations allowed) ----------------
__device__ float g_H  [MAXN * D];    // gelu(LN1(x)), later reused for LN2(conv)
__device__ float g_HW [MAXN * D];    // h @ W_conv
__device__ float g_AGG[MAXN * D];    // normalized aggregation
__device__ float g_F1 [MAXN * D4];   // FFN hidden
__device__ int   g_deg [MAXN];
__device__ float g_dinv[MAXN];
__device__ int   g_eflag;            // 1 => edge_index stored as int32

__device__ __forceinline__ float gelu_f(float x) {
    return 0.5f * x * (1.0f + erff(x * 0.70710678118654752f));
}

// ---------------- edge dtype detection ----------------
// If data is int32, consecutive pairs packed into a 64-bit word are >= 2^32
// whenever the high half (a node index, uniform in [0,N)) is nonzero.
__global__ void k_detect(const unsigned long long* __restrict__ p, long long E,
                         unsigned long long N) {
    __shared__ int bad;
    if (threadIdx.x == 0) bad = 0;
    __syncthreads();
    long long step = E / (long long)blockDim.x;
    if (step < 1) step = 1;
    long long idx = (long long)threadIdx.x * step;
    if (idx < E && p[idx] >= N) bad = 1;   // benign write race (same value)
    __syncthreads();
    if (threadIdx.x == 0) g_eflag = bad;
}

// ---------------- row LayerNorm (+optional conv assembly, +optional gelu) ----
// blockDim = (32, rowsPerBlock). One warp per row, lane holds 4 consecutive floats.
__global__ void k_rowln(const float* __restrict__ x, const float* __restrict__ agg,
                        const float* __restrict__ bconv,
                        const float* __restrict__ g, const float* __restrict__ b,
                        float* __restrict__ out, int N, int do_gelu) {
    int row = blockIdx.x * blockDim.y + threadIdx.y;
    if (row >= N) return;
    int l = threadIdx.x;
    float4 v = ((const float4*)(x + (long long)row * D))[l];
    if (agg) {
        float4 a  = ((const float4*)(agg + (long long)row * D))[l];
        float4 bc = ((const float4*)bconv)[l];
        v.x += a.x + bc.x; v.y += a.y + bc.y;
        v.z += a.z + bc.z; v.w += a.w + bc.w;
    }
    float s  = v.x + v.y + v.z + v.w;
    float ss = v.x*v.x + v.y*v.y + v.z*v.z + v.w*v.w;
    #pragma unroll
    for (int o = 16; o; o >>= 1) {
        s  += __shfl_xor_sync(0xffffffffu, s,  o);
        ss += __shfl_xor_sync(0xffffffffu, ss, o);
    }
    float mu  = s * (1.0f / D);
    float var = ss * (1.0f / D) - mu * mu;
    float rs  = rsqrtf(var + 1e-5f);
    float4 gg = ((const float4*)g)[l];
    float4 bb = ((const float4*)b)[l];
    float4 r;
    r.x = (v.x - mu) * rs * gg.x + bb.x;
    r.y = (v.y - mu) * rs * gg.y + bb.y;
    r.z = (v.z - mu) * rs * gg.z + bb.z;
    r.w = (v.w - mu) * rs * gg.w + bb.w;
    if (do_gelu) { r.x = gelu_f(r.x); r.y = gelu_f(r.y); r.z = gelu_f(r.z); r.w = gelu_f(r.w); }
    ((float4*)(out + (long long)row * D))[l] = r;
}

// ---------------- degree / dinv ----------------
__global__ void k_deginit(int N) {
    int i = blockIdx.x * blockDim.x + threadIdx.x;
    if (i < N) g_deg[i] = 1;                 // self loop
}

__global__ void k_degcount(const void* __restrict__ ei, int E) {
    int e = blockIdx.x * blockDim.x + threadIdx.x;
    if (e >= E) return;
    int dst;
    if (g_eflag) dst = ((const int*)ei)[E + e];
    else         dst = (int)((const long long*)ei)[E + e];
    atomicAdd(&g_deg[dst], 1);
}

__global__ void k_dinv(int N) {
    int i = blockIdx.x * blockDim.x + threadIdx.x;
    if (i < N) g_dinv[i] = rsqrtf((float)g_deg[i]);
}

// ---------------- aggregation ----------------
// Self-loop term initializes AGG: agg[i] = hW[i] * dinv[i]^2
__global__ void k_selfagg(int N) {
    int t = blockIdx.x * blockDim.x + threadIdx.x;
    if (t >= N * 32) return;
    int row = t >> 5;
    float di = g_dinv[row];
    float c = di * di;
    float4 v = ((const float4*)g_HW)[t];
    v.x *= c; v.y *= c; v.z *= c; v.w *= c;
    ((float4*)g_AGG)[t] = v;
}

// One warp per edge: lane loads one float4 of hW[src], 4 scalar atomic adds into AGG[dst].
__global__ void k_edgeagg(const void* __restrict__ ei, int E) {
    int gid = blockIdx.x * blockDim.x + threadIdx.x;
    int e = gid >> 5;
    int lane = threadIdx.x & 31;
    if (e >= E) return;
    int s = 0, d2 = 0;
    float c = 0.0f;
    if (lane == 0) {
        if (g_eflag) { const int* p = (const int*)ei; s = p[e]; d2 = p[E + e]; }
        else { const long long* p = (const long long*)ei; s = (int)p[e]; d2 = (int)p[E + e]; }
        c = g_dinv[s] * g_dinv[d2];
    }
    s  = __shfl_sync(0xffffffffu, s,  0);
    d2 = __shfl_sync(0xffffffffu, d2, 0);
    c  = __shfl_sync(0xffffffffu, c,  0);
    float4 v = ((const float4*)g_HW)[s * 32 + lane];
    float* ap = g_AGG + (long long)d2 * D + lane * 4;
    atomicAdd(ap + 0, v.x * c);
    atomicAdd(ap + 1, v.y * c);
    atomicAdd(ap + 2, v.z * c);
    atomicAdd(ap + 3, v.w * c);
}

// ---------------- tiled fp32 GEMM ----------------
// Block: 256 threads -> 64 rows x 128 cols tile. blockIdx.y = column block (128 cols).
// mode 0: store raw. mode 1: gelu(acc + bias). mode 2: res + gelu(acc + bias).
__global__ void k_gemm(const float* __restrict__ A, const float* __restrict__ W,
                       const float* __restrict__ bias, float* __restrict__ out,
                       int N, int K, int ncols, int mode, const float* __restrict__ res) {
    extern __shared__ float sm[];
    float* Ws = sm;              // 128 x 128 chunk of W (k-major like global)
    float* Hs = sm + D * D;      // 64 x 128 chunk of A rows

    int jb = blockIdx.y;
    int rowBase = blockIdx.x * 64;
    int j = threadIdx.x & 127;
    int half = threadIdx.x >> 7;

    float acc[32];
    #pragma unroll
    for (int r = 0; r < 32; r++) acc[r] = 0.0f;

    for (int kc = 0; kc < K; kc += 128) {
        // stage W chunk: [128 k][128 j], coalesced float4 along j
        for (int idx = threadIdx.x; idx < 128 * 32; idx += 256) {
            int k = idx >> 5, j4 = idx & 31;
            float4 v = *(const float4*)&W[(long long)(kc + k) * ncols + jb * 128 + j4 * 4];
            *(float4*)&Ws[k * D + j4 * 4] = v;
        }
        // stage A rows: [64 r][128 k]
        for (int idx = threadIdx.x; idx < 64 * 32; idx += 256) {
            int r = idx >> 5, kk = idx & 31;
            int row = rowBase + r;
            float4 v = make_float4(0.f, 0.f, 0.f, 0.f);
            if (row < N) v = *(const float4*)&A[(long long)row * K + kc + kk * 4];
            *(float4*)&Hs[r * D + kk * 4] = v;
        }
        __syncthreads();

        const float* hb = Hs + half * 32 * D;
        #pragma unroll 1
        for (int k4 = 0; k4 < 32; k4++) {
            float w0 = Ws[(4 * k4 + 0) * D + j];
            float w1 = Ws[(4 * k4 + 1) * D + j];
            float w2 = Ws[(4 * k4 + 2) * D + j];
            float w3 = Ws[(4 * k4 + 3) * D + j];
            #pragma unroll
            for (int r = 0; r < 32; r++) {
                float4 h = *(const float4*)&hb[r * D + 4 * k4];
                float a = acc[r];
                a = fmaf(h.x, w0, a);
                a = fmaf(h.y, w1, a);
                a = fmaf(h.z, w2, a);
                a = fmaf(h.w, w3, a);
                acc[r] = a;
            }
        }
        __syncthreads();
    }

    int col = jb * 128 + j;
    float bv = (mode >= 1) ? bias[col] : 0.0f;
    #pragma unroll 1
    for (int r = 0; r < 32; r++) {
        int row = rowBase + half * 32 + r;
        if (row < N) {
            float v = acc[r];
            if (mode >= 1) v = gelu_f(v + bv);
            if (mode == 2) v += res[(long long)row * ncols + col];
            out[(long long)row * ncols + col] = v;
        }
    }
}

// ---------------- launch ----------------
extern "C" void kernel_launch(void* const* d_in, const int* in_sizes, int n_in,
                              void* d_out, int out_size) {
    const float* x    = (const float*)d_in[0];
    const void*  ei   = d_in[1];
    const float* ln1g = (const float*)d_in[3];
    const float* ln1b = (const float*)d_in[4];
    const float* Wc   = (const float*)d_in[5];
    const float* bc   = (const float*)d_in[6];
    const float* ln2g = (const float*)d_in[7];
    const float* ln2b = (const float*)d_in[8];
    const float* W1   = (const float*)d_in[9];
    const float* b1   = (const float*)d_in[10];
    const float* W2   = (const float*)d_in[11];
    const float* b2   = (const float*)d_in[12];
    float* out = (float*)d_out;

    int N = in_sizes[0] / D;
    int E = in_sizes[1] / 2;

    static int attr_set = 0;
    const int gemm_smem = (D * D + 64 * D) * (int)sizeof(float);  // 98304
    if (!attr_set) {
        cudaFuncSetAttribute(k_gemm, cudaFuncAttributeMaxDynamicSharedMemorySize, gemm_smem);
        attr_set = 1;
    }

    float* gH   = nullptr; cudaGetSymbolAddress((void**)&gH,   g_H);
    float* gHW  = nullptr; cudaGetSymbolAddress((void**)&gHW,  g_HW);
    float* gAGG = nullptr; cudaGetSymbolAddress((void**)&gAGG, g_AGG);
    float* gF1  = nullptr; cudaGetSymbolAddress((void**)&gF1,  g_F1);

    dim3 lnBlk(32, 8);
    int lnGrid = (N + 7) / 8;
    int rowBlocks = (N + 63) / 64;

    // 0. edge dtype detection
    k_detect<<<1, 256>>>((const unsigned long long*)ei, (long long)E,
                         (unsigned long long)N);
    // 1. H = gelu(LN1(x))
    k_rowln<<<lnGrid, lnBlk>>>(x, nullptr, nullptr, ln1g, ln1b, gH, N, 1);
    // 2. HW = H @ W_conv
    k_gemm<<<dim3(rowBlocks, 1), 256, gemm_smem>>>(gH, Wc, nullptr, gHW, N, D, D, 0, nullptr);
    // 3. degrees (with self loop) and dinv
    k_deginit<<<(N + 255) / 256, 256>>>(N);
    k_degcount<<<(E + 255) / 256, 256>>>(ei, E);
    k_dinv<<<(N + 255) / 256, 256>>>(N);
    // 4. AGG = self-loop term, then scatter edges
    k_selfagg<<<(N * 32 + 255) / 256, 256>>>(N);
    {
        long long tot = (long long)E * 32;
        int blocks = (int)((tot + 255) / 256);
        k_edgeagg<<<blocks, 256>>>(ei, E);
    }
    // 5. gH = LN2(x + AGG + b_conv)
    k_rowln<<<lnGrid, lnBlk>>>(x, gAGG, bc, ln2g, ln2b, gH, N, 0);
    // 6. F1 = gelu(gH @ W1 + b1)
    k_gemm<<<dim3(rowBlocks, 4), 256, gemm_smem>>>(gH, W1, b1, gF1, N, D, D4, 1, nullptr);
    // 7. out = x + gelu(F1 @ W2 + b2)
    k_gemm<<<dim3(rowBlocks, 1), 256, gemm_smem>>>(gF1, W2, b2, out, N, D4, D, 2, x);
}

// round 3
// speedup vs baseline: 2.1415x; 2.1415x over previous
#include <cuda_runtime.h>
#include <math.h>
#include <stdint.h>

#define D   128
#define D4  512
#define MAXN 100000

// ---------------- scratch (no allocations allowed) ----------------
__device__ float g_H  [MAXN * D];    // gelu(LN1(x)), later LN2(conv)
__device__ float g_HW [MAXN * D];    // h @ W_conv
__device__ float g_AGG[MAXN * D];    // normalized aggregation
__device__ float g_F1 [MAXN * D4];   // FFN hidden
__device__ int   g_deg [MAXN];
__device__ float g_dinv[MAXN];
__device__ int   g_eflag;            // 1 => edge_index stored as int32

__device__ __forceinline__ float gelu_f(float x) {
    return 0.5f * x * (1.0f + erff(x * 0.70710678118654752f));
}

__device__ __forceinline__ uint32_t tf32_bits(float x) {
    uint32_t r;
    asm("cvt.rna.tf32.f32 %0, %1;" : "=r"(r) : "f"(x));
    return r;
}

// ---------------- edge dtype detection ----------------
__global__ void k_detect(const unsigned long long* __restrict__ p, long long E,
                         unsigned long long N) {
    __shared__ int bad;
    if (threadIdx.x == 0) bad = 0;
    __syncthreads();
    long long step = E / (long long)blockDim.x;
    if (step < 1) step = 1;
    long long idx = (long long)threadIdx.x * step;
    if (idx < E && p[idx] >= N) bad = 1;
    __syncthreads();
    if (threadIdx.x == 0) g_eflag = bad;
}

// ---------------- row LayerNorm (+optional conv assembly, +optional gelu) ----
__global__ void k_rowln(const float* __restrict__ x, const float* __restrict__ agg,
                        const float* __restrict__ bconv,
                        const float* __restrict__ g, const float* __restrict__ b,
                        float* __restrict__ out, int N, int do_gelu) {
    int row = blockIdx.x * blockDim.y + threadIdx.y;
    if (row >= N) return;
    int l = threadIdx.x;
    float4 v = ((const float4*)(x + (size_t)row * D))[l];
    if (agg) {
        float4 a  = ((const float4*)(agg + (size_t)row * D))[l];
        float4 bc = ((const float4*)bconv)[l];
        v.x += a.x + bc.x; v.y += a.y + bc.y;
        v.z += a.z + bc.z; v.w += a.w + bc.w;
    }
    float s  = v.x + v.y + v.z + v.w;
    float ss = v.x*v.x + v.y*v.y + v.z*v.z + v.w*v.w;
    #pragma unroll
    for (int o = 16; o; o >>= 1) {
        s  += __shfl_xor_sync(0xffffffffu, s,  o);
        ss += __shfl_xor_sync(0xffffffffu, ss, o);
    }
    float mu  = s * (1.0f / D);
    float var = ss * (1.0f / D) - mu * mu;
    float rs  = rsqrtf(var + 1e-5f);
    float4 gg = ((const float4*)g)[l];
    float4 bb = ((const float4*)b)[l];
    float4 r;
    r.x = (v.x - mu) * rs * gg.x + bb.x;
    r.y = (v.y - mu) * rs * gg.y + bb.y;
    r.z = (v.z - mu) * rs * gg.z + bb.z;
    r.w = (v.w - mu) * rs * gg.w + bb.w;
    if (do_gelu) { r.x = gelu_f(r.x); r.y = gelu_f(r.y); r.z = gelu_f(r.z); r.w = gelu_f(r.w); }
    ((float4*)(out + (size_t)row * D))[l] = r;
}

// ---------------- degree / dinv ----------------
__global__ void k_deginit(int N) {
    int i = blockIdx.x * blockDim.x + threadIdx.x;
    if (i < N) g_deg[i] = 1;
}
__global__ void k_degcount(const void* __restrict__ ei, int E) {
    int e = blockIdx.x * blockDim.x + threadIdx.x;
    if (e >= E) return;
    int dst;
    if (g_eflag) dst = ((const int*)ei)[E + e];
    else         dst = (int)((const long long*)ei)[E + e];
    atomicAdd(&g_deg[dst], 1);
}
__global__ void k_dinv(int N) {
    int i = blockIdx.x * blockDim.x + threadIdx.x;
    if (i < N) g_dinv[i] = rsqrtf((float)g_deg[i]);
}

// ---------------- aggregation ----------------
__global__ void k_selfagg(int N) {
    int t = blockIdx.x * blockDim.x + threadIdx.x;
    if (t >= N * 32) return;
    int row = t >> 5;
    float di = g_dinv[row];
    float c = di * di;
    float4 v = ((const float4*)g_HW)[t];
    v.x *= c; v.y *= c; v.z *= c; v.w *= c;
    ((float4*)g_AGG)[t] = v;
}

// One warp per edge; lane does one vector red.v4 (4x fewer atomic ops).
__global__ void k_edgeagg(const void* __restrict__ ei, int E) {
    int gid = blockIdx.x * blockDim.x + threadIdx.x;
    int e = gid >> 5;
    int lane = threadIdx.x & 31;
    if (e >= E) return;
    int s = 0, d2 = 0;
    float c = 0.0f;
    if (lane == 0) {
        if (g_eflag) { const int* p = (const int*)ei; s = p[e]; d2 = p[E + e]; }
        else { const long long* p = (const long long*)ei; s = (int)p[e]; d2 = (int)p[E + e]; }
        c = g_dinv[s] * g_dinv[d2];
    }
    s  = __shfl_sync(0xffffffffu, s,  0);
    d2 = __shfl_sync(0xffffffffu, d2, 0);
    c  = __shfl_sync(0xffffffffu, c,  0);
    float4 v = ((const float4*)g_HW)[s * 32 + lane];
    float* ap = g_AGG + (size_t)d2 * D + lane * 4;
    asm volatile("red.global.add.v4.f32 [%0], {%1, %2, %3, %4};"
                 :: "l"(ap), "f"(v.x * c), "f"(v.y * c), "f"(v.z * c), "f"(v.w * c)
                 : "memory");
}

// ---------------- tf32 mma.sync GEMM --------------------------------------
// CTA 256 threads -> 128x128 tile. 8 warps as 4(m) x 2(n); warp tile 32x64.
// K chunked at 64 through padded smem. Fragments per PTX m16n8k8 tf32 layout.
// mode 0: raw fp32. mode 1: gelu(acc+bias). mode 2: res + gelu(acc+bias).
#define KCH 64
#define APITCH 68
#define WPITCH 136

__global__ void __launch_bounds__(256, 1) k_gemm_tc(
    const float* __restrict__ A, const float* __restrict__ W,
    const float* __restrict__ bias, const float* __restrict__ res,
    float* __restrict__ out, int N, int K, int ncols, int mode)
{
    extern __shared__ float sm[];
    float* As = sm;                    // [128][APITCH] tf32 bits
    float* Ws = sm + 128 * APITCH;     // [KCH][WPITCH] tf32 bits

    int tid = threadIdx.x, wid = tid >> 5, lane = tid & 31;
    int rowBase = blockIdx.x * 128, colBase = blockIdx.y * 128;
    int wm = (wid & 3) * 32;           // warp row offset in tile
    int wn = (wid >> 2) * 64;          // warp col offset in tile
    int lq = lane >> 2, lr = lane & 3; // quad id / lane-in-quad

    float acc[2][8][4];
    #pragma unroll
    for (int i = 0; i < 2; i++)
        #pragma unroll
        for (int j = 0; j < 8; j++)
            #pragma unroll
            for (int k = 0; k < 4; k++) acc[i][j][k] = 0.0f;

    for (int kc = 0; kc < K; kc += KCH) {
        // stage A: 128 rows x 64 k (float4 loads, tf32 convert)
        for (int idx = tid; idx < 128 * (KCH / 4); idx += 256) {
            int r = idx >> 4, k4 = (idx & 15) << 2;
            float4 v = make_float4(0.f, 0.f, 0.f, 0.f);
            int gr = rowBase + r;
            if (gr < N) v = *(const float4*)&A[(size_t)gr * K + kc + k4];
            uint4 t;
            t.x = tf32_bits(v.x); t.y = tf32_bits(v.y);
            t.z = tf32_bits(v.z); t.w = tf32_bits(v.w);
            *(uint4*)&As[r * APITCH + k4] = t;
        }
        // stage W: 64 k x 128 n
        for (int idx = tid; idx < KCH * 32; idx += 256) {
            int r = idx >> 5, n4 = (idx & 31) << 2;
            float4 v = *(const float4*)&W[(size_t)(kc + r) * ncols + colBase + n4];
            uint4 t;
            t.x = tf32_bits(v.x); t.y = tf32_bits(v.y);
            t.z = tf32_bits(v.z); t.w = tf32_bits(v.w);
            *(uint4*)&Ws[r * WPITCH + n4] = t;
        }
        __syncthreads();

        #pragma unroll
        for (int ks = 0; ks < KCH; ks += 8) {
            uint32_t a[2][4], b[8][2];
            #pragma unroll
            for (int mf = 0; mf < 2; mf++) {
                int r0 = wm + mf * 16 + lq;
                a[mf][0] = __float_as_uint(As[r0 * APITCH + ks + lr]);
                a[mf][1] = __float_as_uint(As[(r0 + 8) * APITCH + ks + lr]);
                a[mf][2] = __float_as_uint(As[r0 * APITCH + ks + lr + 4]);
                a[mf][3] = __float_as_uint(As[(r0 + 8) * APITCH + ks + lr + 4]);
            }
            #pragma unroll
            for (int nf = 0; nf < 8; nf++) {
                int c0 = wn + nf * 8 + lq;
                b[nf][0] = __float_as_uint(Ws[(ks + lr) * WPITCH + c0]);
                b[nf][1] = __float_as_uint(Ws[(ks + lr + 4) * WPITCH + c0]);
            }
            #pragma unroll
            for (int mf = 0; mf < 2; mf++)
                #pragma unroll
                for (int nf = 0; nf < 8; nf++) {
                    asm volatile(
                        "mma.sync.aligned.m16n8k8.row.col.f32.tf32.tf32.f32 "
                        "{%0,%1,%2,%3}, {%4,%5,%6,%7}, {%8,%9}, {%0,%1,%2,%3};"
                        : "+f"(acc[mf][nf][0]), "+f"(acc[mf][nf][1]),
                          "+f"(acc[mf][nf][2]), "+f"(acc[mf][nf][3])
                        : "r"(a[mf][0]), "r"(a[mf][1]), "r"(a[mf][2]), "r"(a[mf][3]),
                          "r"(b[nf][0]), "r"(b[nf][1]));
                }
        }
        __syncthreads();
    }

    // epilogue
    #pragma unroll
    for (int mf = 0; mf < 2; mf++) {
        int r0 = rowBase + wm + mf * 16 + lq;
        #pragma unroll
        for (int half = 0; half < 2; half++) {
            int row = r0 + half * 8;
            if (row >= N) continue;
            #pragma unroll
            for (int nf = 0; nf < 8; nf++) {
                int col = colBase + wn + nf * 8 + lr * 2;
                float v0 = acc[mf][nf][half * 2];
                float v1 = acc[mf][nf][half * 2 + 1];
                if (mode >= 1) {
                    v0 = gelu_f(v0 + bias[col]);
                    v1 = gelu_f(v1 + bias[col + 1]);
                }
                if (mode == 2) {
                    float2 r2 = *(const float2*)&res[(size_t)row * ncols + col];
                    v0 += r2.x; v1 += r2.y;
                }
                *(float2*)&out[(size_t)row * ncols + col] = make_float2(v0, v1);
            }
        }
    }
}

// ---------------- launch ----------------
extern "C" void kernel_launch(void* const* d_in, const int* in_sizes, int n_in,
                              void* d_out, int out_size) {
    const float* x    = (const float*)d_in[0];
    const void*  ei   = d_in[1];
    const float* ln1g = (const float*)d_in[3];
    const float* ln1b = (const float*)d_in[4];
    const float* Wc   = (const float*)d_in[5];
    const float* bc   = (const float*)d_in[6];
    const float* ln2g = (const float*)d_in[7];
    const float* ln2b = (const float*)d_in[8];
    const float* W1   = (const float*)d_in[9];
    const float* b1   = (const float*)d_in[10];
    const float* W2   = (const float*)d_in[11];
    const float* b2   = (const float*)d_in[12];
    float* out = (float*)d_out;

    int N = in_sizes[0] / D;
    int E = in_sizes[1] / 2;

    const int gemm_smem = (128 * APITCH + KCH * WPITCH) * (int)sizeof(float);
    static int attr_set = 0;
    if (!attr_set) {
        cudaFuncSetAttribute(k_gemm_tc, cudaFuncAttributeMaxDynamicSharedMemorySize, gemm_smem);
        attr_set = 1;
    }

    float* gH;   cudaGetSymbolAddress((void**)&gH,   g_H);
    float* gHW;  cudaGetSymbolAddress((void**)&gHW,  g_HW);
    float* gAGG; cudaGetSymbolAddress((void**)&gAGG, g_AGG);
    float* gF1;  cudaGetSymbolAddress((void**)&gF1,  g_F1);

    dim3 lnBlk(32, 8);
    int lnGrid = (N + 7) / 8;
    int rowBlocks = (N + 127) / 128;

    // launches 0-4 (degree work first so launch #5 = conv GEMM for ncu -s 5)
    k_detect<<<1, 256>>>((const unsigned long long*)ei, (long long)E,
                         (unsigned long long)N);
    k_deginit<<<(N + 255) / 256, 256>>>(N);
    k_degcount<<<(E + 255) / 256, 256>>>(ei, E);
    k_dinv<<<(N + 255) / 256, 256>>>(N);
    k_rowln<<<lnGrid, lnBlk>>>(x, nullptr, nullptr, ln1g, ln1b, gH, N, 1);
    // 5. HW = H @ W_conv   (profiled launch)
    k_gemm_tc<<<dim3(rowBlocks, 1), 256, gemm_smem>>>(
        gH, Wc, nullptr, nullptr, gHW, N, D, D, 0);
    // 6-7. AGG = self-loop term + edge scatter
    k_selfagg<<<(N * 32 + 255) / 256, 256>>>(N);
    {
        long long tot = (long long)E * 32;
        int blocks = (int)((tot + 255) / 256);
        k_edgeagg<<<blocks, 256>>>(ei, E);
    }
    // 8. H = LN2(x + AGG + b_conv)
    k_rowln<<<lnGrid, lnBlk>>>(x, gAGG, bc, ln2g, ln2b, gH, N, 0);
    // 9. F1 = gelu(H @ W1 + b1)
    k_gemm_tc<<<dim3(rowBlocks, 4), 256, gemm_smem>>>(
        gH, W1, b1, nullptr, gF1, N, D, D4, 1);
    // 10. out = x + gelu(F1 @ W2 + b2)
    k_gemm_tc<<<dim3(rowBlocks, 1), 256, gemm_smem>>>(
        gF1, W2, b2, x, out, N, D4, D, 2);
}